// round 11
// baseline (speedup 1.0000x reference)
#include <cuda_runtime.h>
#include <cuda_fp16.h>
#include <math.h>
#include <stdint.h>

#define B_ 8
#define N_ 2048
#define H_ 1024
#define E_ 8
#define D_ 2048
#define T_ 16384   // B_*N_
#define TPAD_ (T_ + 1024)

// ---------------- scratch (device-side referenced ONLY from device code) ----------------
// Invariant: g_counts/g_prob_sum/g_entropy_sum/g_flag are ZERO on entry to every
// call (BSS for call 1; finalize resets). Pad rows of g_Xh are never written -> stay 0.
__device__ int    g_expert_idx[T_];
__device__ int    g_counts[E_];
__device__ int    g_offsets[E_ + 1];
__device__ int    g_poffsets[E_ + 1];
__device__ int    g_cursor[E_];
__device__ int    g_ptok[TPAD_];
__device__ float  g_prob_sum[E_];
__device__ float  g_entropy_sum;
__device__ volatile int g_flag;
__device__ __half g_Xh[(size_t)TPAD_ * H_];      // gathered tokens, fp16, padded per expert
__device__ __half g_Hh[(size_t)TPAD_ * D_];      // GELU activations, fp16

// ---------------- helpers ----------------
__device__ __forceinline__ uint32_t smem_u32(const void* p) {
    uint32_t a;
    asm("{ .reg .u64 t; cvta.to.shared.u64 t, %1; cvt.u32.u64 %0, t; }" : "=r"(a) : "l"(p));
    return a;
}
__device__ __forceinline__ void cp_async16(uint32_t dst, const void* src) {
    asm volatile("cp.async.cg.shared.global [%0], [%1], 16;" :: "r"(dst), "l"(src));
}
#define CP_COMMIT() asm volatile("cp.async.commit_group;" ::: "memory")
#define CP_WAIT1()  asm volatile("cp.async.wait_group 1;" ::: "memory")
#define CP_WAIT0()  asm volatile("cp.async.wait_group 0;" ::: "memory")

__device__ __forceinline__ void ldmatrix_x4(uint32_t& r0, uint32_t& r1,
                                            uint32_t& r2, uint32_t& r3, uint32_t addr) {
    asm volatile("ldmatrix.sync.aligned.m8n8.x4.shared.b16 {%0,%1,%2,%3}, [%4];"
                 : "=r"(r0), "=r"(r1), "=r"(r2), "=r"(r3) : "r"(addr));
}
__device__ __forceinline__ uint32_t pack_h2(float lo, float hi) {
    __half2 h = __floats2half2_rn(lo, hi);
    return *reinterpret_cast<uint32_t*>(&h);
}
__device__ __forceinline__ void mma_f16_16x8x16(float& d0, float& d1, float& d2, float& d3,
                                                uint32_t a0, uint32_t a1, uint32_t a2, uint32_t a3,
                                                uint32_t b0, uint32_t b1) {
    asm volatile(
        "mma.sync.aligned.m16n8k16.row.col.f32.f16.f16.f32 "
        "{%0,%1,%2,%3}, {%4,%5,%6,%7}, {%8,%9}, {%0,%1,%2,%3};"
        : "+f"(d0), "+f"(d1), "+f"(d2), "+f"(d3)
        : "r"(a0), "r"(a1), "r"(a2), "r"(a3), "r"(b0), "r"(b1));
}

// ---------------- router ----------------
__global__ void router_kernel(const float* __restrict__ x,
                              const float* __restrict__ Wr,
                              const float* __restrict__ br) {
    __shared__ float sWr[H_ * E_];
    for (int i = threadIdx.x; i < H_ * E_; i += blockDim.x) sWr[i] = Wr[i];
    __syncthreads();

    int warp = threadIdx.x >> 5;
    int lane = threadIdx.x & 31;
    int t = blockIdx.x * 8 + warp;
    if (t >= T_) return;

    const float* xr = x + (size_t)t * H_;
    float acc[E_];
#pragma unroll
    for (int e = 0; e < E_; e++) acc[e] = 0.f;
    for (int h = lane; h < H_; h += 32) {
        float xv = xr[h];
        const float* w = &sWr[h * E_];
#pragma unroll
        for (int e = 0; e < E_; e++) acc[e] += xv * w[e];
    }
#pragma unroll
    for (int e = 0; e < E_; e++) {
#pragma unroll
        for (int o = 16; o > 0; o >>= 1)
            acc[e] += __shfl_xor_sync(0xffffffffu, acc[e], o);
    }
    if (lane == 0) {
        float lg[E_];
        float mx = -1e30f;
        int arg = 0;
#pragma unroll
        for (int e = 0; e < E_; e++) {
            lg[e] = acc[e] + br[e];
            if (lg[e] > mx) { mx = lg[e]; arg = e; }
        }
        float s = 0.f;
#pragma unroll
        for (int e = 0; e < E_; e++) { lg[e] = expf(lg[e] - mx); s += lg[e]; }
        float inv = 1.f / s;
        float ent = 0.f;
#pragma unroll
        for (int e = 0; e < E_; e++) {
            float p = lg[e] * inv;
            atomicAdd(&g_prob_sum[e], p);
            ent -= p * logf(p + 1e-8f);
        }
        atomicAdd(&g_entropy_sum, ent);
        atomicAdd(&g_counts[arg], 1);
        g_expert_idx[t] = arg;
    }
}

// ---------------- scan + scatter + gather-to-fp16 (block per token) ----------------
__global__ void scanscatter_kernel(const float* __restrict__ x) {
    __shared__ int sp;
    const int t = blockIdx.x;
    if (threadIdx.x == 0) {
        if (t == 0) {
            int o = 0, po = 0;
            for (int e = 0; e < E_; e++) {
                g_offsets[e] = o;
                g_cursor[e] = o;
                g_poffsets[e] = po;
                o += g_counts[e];
                po += (g_counts[e] + 127) & ~127;
            }
            g_offsets[E_] = o;
            g_poffsets[E_] = po;
            __threadfence();
            g_flag = 1;
        } else {
            while (g_flag == 0) __nanosleep(64);
        }
        __threadfence();
        int e = g_expert_idx[t];
        int pos = atomicAdd(&g_cursor[e], 1);
        int p = g_poffsets[e] + (pos - g_offsets[e]);
        g_ptok[p] = t;
        sp = p;
    }
    __syncthreads();

    // block 0: mark pad slots (-1). Disjoint from real writes; GEMMs run after this kernel.
    if (t == 0) {
#pragma unroll
        for (int e = 0; e < E_; e++) {
            int start = g_poffsets[e] + g_counts[e];
            int end = g_poffsets[e + 1];
            for (int p = start + threadIdx.x; p < end; p += blockDim.x)
                g_ptok[p] = -1;
        }
    }

    const int p = sp;
    const float4* src = reinterpret_cast<const float4*>(x + (size_t)t * H_);
    __half2* dst = reinterpret_cast<__half2*>(g_Xh + (size_t)p * H_);
    for (int i = threadIdx.x; i < H_ / 4; i += blockDim.x) {
        float4 v = src[i];
        dst[i * 2 + 0] = __floats2half2_rn(v.x, v.y);
        dst[i * 2 + 1] = __floats2half2_rn(v.z, v.w);
    }
}

// ---------------- fp16-A / fp32-B mma grouped GEMM ----------------
// Block tile 128(M) x 128(N), 128 threads, 4 warps (2m x 2n), warp tile 64x64.
// KC=32, 3-stage cp.async pipeline, 2 CTAs/SM.
// A: fp16 (g_Xh / g_Hh), SMEM [128][40] halfs, frags via ldmatrix.x4.
// B: fp32 DIRECT from W[e][k][n] (no conversion pre-pass!), SMEM [32][132] floats,
//    frags via 4x LDS.32 + __floats2half2_rn pack (bit-identical to a fp16 pre-pass).
#define STAGES  3
#define KC      32
#define PADA    40                          // halfs per A row
#define PADBF   132                         // floats per B row (128 + 4)
#define A_HALFS (128 * PADA)                // 5120 halfs  = 10240 B
#define A_BYTES (A_HALFS * 2)
#define B_FLOATS (KC * PADBF)               // 4224 floats = 16896 B
#define STAGE_BYTES (A_BYTES + B_FLOATS * 4)     // 27136
#define GEMM_SMEM (STAGES * STAGE_BYTES)         // 81408

template<int KTOT, int NTOT, bool GELU>
__global__ void __launch_bounds__(128, 2)
moe_gemm(const float* __restrict__ xres,    // x (residual, GEMM2)
         const float* __restrict__ W,       // W1/W2 fp32: [E][KTOT][NTOT], N contiguous
         const float* __restrict__ bias,
         float* __restrict__ outp)
{
    constexpr int CCH = KTOT / KC;
    const __half* A = GELU ? g_Xh : g_Hh;

    const int e = blockIdx.z;
    const int pbase = g_poffsets[e];
    const int pcount = g_poffsets[e + 1] - pbase;
    const int m0 = blockIdx.y * 128;
    if (m0 >= pcount) return;
    const int n0 = blockIdx.x * 128;

    extern __shared__ char smc[];
    const uint32_t smbase = smem_u32(smc);

    const int tid = threadIdx.x;
    const int wid = tid >> 5;      // 0..3
    const int lane = tid & 31;
    const int grp = lane >> 2;     // 0..7
    const int qid = lane & 3;      // 0..3
    const int mrow = (wid & 1) * 64;
    const int nrow = (wid >> 1) * 64;

    // cp.async A: 4 x 16B per thread (512 chunks: row=idx>>2, c=idx&3)
    const char* aptr[4];
    uint32_t aoff[4];
#pragma unroll
    for (int i = 0; i < 4; i++) {
        int idx = tid + i * 128;
        int row = idx >> 2, c = idx & 3;
        aptr[i] = reinterpret_cast<const char*>(
                      A + (size_t)(pbase + m0 + row) * KTOT) + c * 16;
        aoff[i] = (uint32_t)(row * PADA + c * 8) * 2;
    }
    // cp.async B: 8 x 16B per thread (1024 chunks: kr=idx>>5, c=idx&31)
    const char* bptr[8];
    uint32_t boff[8];
#pragma unroll
    for (int i = 0; i < 8; i++) {
        int idx = tid + i * 128;
        int kr = idx >> 5, c = idx & 31;
        bptr[i] = reinterpret_cast<const char*>(
                      W + (size_t)e * KTOT * NTOT + (size_t)kr * NTOT + n0) + c * 16;
        boff[i] = (uint32_t)A_BYTES + (uint32_t)(kr * PADBF + c * 4) * 4;
    }

#define LOAD_STAGE(st, ch) do {                                                     \
        uint32_t _sb = smbase + (uint32_t)(st) * STAGE_BYTES;                       \
        size_t _ga = (size_t)(ch) * (KC * 2);                                       \
        size_t _gb = (size_t)(ch) * ((size_t)KC * NTOT * 4);                        \
        _Pragma("unroll")                                                           \
        for (int _i = 0; _i < 4; _i++) cp_async16(_sb + aoff[_i], aptr[_i] + _ga);  \
        _Pragma("unroll")                                                           \
        for (int _i = 0; _i < 8; _i++) cp_async16(_sb + boff[_i], bptr[_i] + _gb);  \
    } while (0)

    // A ldmatrix lane base (relative to stage base)
    const uint32_t aFragBase =
        ((uint32_t)((mrow + (lane & 15)) * PADA + (lane >> 4) * 8)) * 2;

    float acc[4][8][4];
#pragma unroll
    for (int i = 0; i < 4; i++)
#pragma unroll
        for (int j = 0; j < 8; j++)
#pragma unroll
            for (int q = 0; q < 4; q++) acc[i][j][q] = 0.f;

    LOAD_STAGE(0, 0); CP_COMMIT();
    LOAD_STAGE(1, 1); CP_COMMIT();

    for (int c = 0; c < CCH; c++) {
        CP_WAIT1();
        __syncthreads();
        if (c + 2 < CCH) LOAD_STAGE((c + 2) % STAGES, c + 2);
        CP_COMMIT();

        const uint32_t stage = smbase + (uint32_t)(c % STAGES) * STAGE_BYTES;
        const float* BsF = reinterpret_cast<const float*>(
            smc + (size_t)(c % STAGES) * STAGE_BYTES + A_BYTES);

#pragma unroll
        for (int ks = 0; ks < 2; ks++) {
            uint32_t a[4][4], b[8][2];
#pragma unroll
            for (int fm = 0; fm < 4; fm++)
                ldmatrix_x4(a[fm][0], a[fm][1], a[fm][2], a[fm][3],
                            stage + aFragBase + fm * (16 * PADA * 2) + ks * 32);
            // B frags from fp32 SMEM: b0 = k{2q,2q+1}, b1 = k{2q+8,2q+9}, col = nrow+fn*8+grp
#pragma unroll
            for (int fn = 0; fn < 8; fn++) {
                const float* bp = BsF + (ks * 16 + 2 * qid) * PADBF + nrow + fn * 8 + grp;
                b[fn][0] = pack_h2(bp[0],         bp[PADBF]);
                b[fn][1] = pack_h2(bp[8 * PADBF], bp[9 * PADBF]);
            }
#pragma unroll
            for (int fm = 0; fm < 4; fm++)
#pragma unroll
                for (int fn = 0; fn < 8; fn++)
                    mma_f16_16x8x16(acc[fm][fn][0], acc[fm][fn][1],
                                    acc[fm][fn][2], acc[fm][fn][3],
                                    a[fm][0], a[fm][1], a[fm][2], a[fm][3],
                                    b[fn][0], b[fn][1]);
        }
    }
    CP_WAIT0();

    // ---- epilogue ----
    int toks[4][2];
    if (!GELU) {
#pragma unroll
        for (int fm = 0; fm < 4; fm++) {
            toks[fm][0] = g_ptok[pbase + m0 + mrow + fm * 16 + grp];
            toks[fm][1] = g_ptok[pbase + m0 + mrow + fm * 16 + grp + 8];
        }
    }

#pragma unroll
    for (int fn = 0; fn < 8; fn++) {
        const int col = n0 + nrow + fn * 8 + qid * 2;
        const float2 bv = *reinterpret_cast<const float2*>(bias + (size_t)e * NTOT + col);
#pragma unroll
        for (int fm = 0; fm < 4; fm++) {
#pragma unroll
            for (int h = 0; h < 2; h++) {
                float v0 = acc[fm][fn][h * 2 + 0] + bv.x;
                float v1 = acc[fm][fn][h * 2 + 1] + bv.y;
                if (GELU) {
                    const int prow = pbase + m0 + mrow + fm * 16 + grp + h * 8;
                    v0 = 0.5f * v0 * (1.0f + erff(v0 * 0.7071067811865476f));
                    v1 = 0.5f * v1 * (1.0f + erff(v1 * 0.7071067811865476f));
                    *reinterpret_cast<__half2*>(g_Hh + (size_t)prow * NTOT + col) =
                        __floats2half2_rn(v0, v1);
                } else {
                    const int tok = toks[fm][h];
                    if (tok >= 0) {
                        const float2 xr = *reinterpret_cast<const float2*>(
                            xres + (size_t)tok * NTOT + col);
                        *reinterpret_cast<float2*>(outp + (size_t)tok * NTOT + col) =
                            make_float2(v0 + xr.x, v1 + xr.y);
                    }
                }
            }
        }
    }
#undef LOAD_STAGE
}

// ---------------- losses + state reset for next call ----------------
__global__ void finalize_kernel(float* __restrict__ out, int out_size) {
    if (threadIdx.x == 0) {
        long long base = (long long)T_ * H_;
        if ((long long)out_size >= base + 2) {
            float s = 0.f;
            for (int e = 0; e < E_; e++) {
                float p = g_prob_sum[e] / (float)T_;
                s += p * p;
            }
            out[base] = (float)E_ * s;
            out[base + 1] = g_entropy_sum / (float)T_;
        }
        if ((long long)out_size >= base + 2 + E_) {
            for (int e = 0; e < E_; e++)
                out[base + 2 + e] = (float)g_counts[e];
        }
        for (int e = 0; e < E_; e++) { g_counts[e] = 0; g_prob_sum[e] = 0.f; }
        g_entropy_sum = 0.f;
        g_flag = 0;
    }
}

// ---------------- launch ----------------
extern "C" void kernel_launch(void* const* d_in, const int* in_sizes, int n_in,
                              void* d_out, int out_size) {
    const float* x  = (const float*)d_in[0];
    const float* Wr = (const float*)d_in[1];
    const float* br = (const float*)d_in[2];
    const float* W1 = (const float*)d_in[3];
    const float* b1 = (const float*)d_in[4];
    const float* W2 = (const float*)d_in[5];
    const float* b2 = (const float*)d_in[6];
    float* out = (float*)d_out;

    cudaFuncSetAttribute(moe_gemm<H_, D_, true>,
                         cudaFuncAttributeMaxDynamicSharedMemorySize, GEMM_SMEM);
    cudaFuncSetAttribute(moe_gemm<D_, H_, false>,
                         cudaFuncAttributeMaxDynamicSharedMemorySize, GEMM_SMEM);

    router_kernel<<<T_ / 8, 256>>>(x, Wr, br);                 // idx 0
    scanscatter_kernel<<<T_, 128>>>(x);                        // idx 1
    moe_gemm<H_, D_, true ><<<dim3(D_ / 128, T_ / 128, E_), 128, GEMM_SMEM>>>(x, W1, b1, out); // idx 2
    // idx 3 — the slot ncu captures:
    moe_gemm<D_, H_, false><<<dim3(H_ / 128, T_ / 128, E_), 128, GEMM_SMEM>>>(x, W2, b2, out); // idx 3
    finalize_kernel<<<1, 32>>>(out, out_size);                 // idx 4
}